// round 16
// baseline (speedup 1.0000x reference)
#include <cuda_runtime.h>
#include <cuda_fp16.h>
#include <cstdint>
#include <cstddef>

#define NN   50000
#define NE   600000
#define C    128
#define NG   128
#define OUTC 10
#define NT   391          // ceil(NN/128) M-tiles
#define NCTA 148
#define ADJMAX (NE + 8 * NN)   // padded adjacency capacity

// ---------------- scratch (static device globals: allocation-free) ----------
__device__ __half g_x16[(NN + 1) * C];   // fp16 x (+ zero row NN)
__device__ __half g_h16[(NN + 1) * C];   // fp16 h (+ zero row NN)
__device__ __half g_agg16[NN * C];       // fp16 aggregated means
__device__ float  g_inv[NN];
__device__ float  g_ginv[NG];
__device__ float  g_pool[NG * C];
// weights fp16 split: [layer][src(2)][n(128)][128 u32 words: 0..63 hi, 64..127 lo]
__device__ uint4 g_Bp4[3][8192];
__device__ int   g_cnt[NN];
__device__ int   g_gcnt[NG];
__device__ int   g_off[NN + 1];
__device__ int   g_cur[NN];
__device__ __align__(16) int g_adj[ADJMAX];
__device__ int   g_batch[NN];
__device__ int   g_part[256];
__device__ int   g_pbase[256];
__device__ int   g_is64;

// ---------------- mma.sync fp16 m16n8k16, f32 accum --------------------------
__device__ __forceinline__ void mma_f16(float* d,
                                        uint32_t a0, uint32_t a1, uint32_t a2, uint32_t a3,
                                        uint32_t b0, uint32_t b1) {
    asm volatile(
        "mma.sync.aligned.m16n8k16.row.col.f32.f16.f16.f32 "
        "{%0,%1,%2,%3}, {%4,%5,%6,%7}, {%8,%9}, {%0,%1,%2,%3};"
        : "+f"(d[0]), "+f"(d[1]), "+f"(d[2]), "+f"(d[3])
        : "r"(a0), "r"(a1), "r"(a2), "r"(a3), "r"(b0), "r"(b1));
}

// ---------------- init: zero + detect + weight split + x16 convert -----------
#define PREPN (3 * 16384)
#define XCONV (NN * 32)
__global__ void init_kernel(const unsigned int* __restrict__ ei_words,
                            const float* __restrict__ Wl0, const float* __restrict__ Wr0,
                            const float* __restrict__ Wl1, const float* __restrict__ Wr1,
                            const float* __restrict__ Wl2, const float* __restrict__ Wr2,
                            const float* __restrict__ x) {
    int id = blockIdx.x * blockDim.x + threadIdx.x;
    if (id == 0) {
        int is64 = 1;
#pragma unroll
        for (int k = 0; k < 16; k++)
            if (ei_words[1 + 74 * k] != 0u) { is64 = 0; break; }
        g_is64 = is64;
    }
    if (id < NN) g_cnt[id] = 0;
    if (id < NG) g_gcnt[id] = 0;
    if (id < NG * C) g_pool[id] = 0.0f;

    if (id < PREPN) {
        int layer = id >> 14;
        int rem = id & 16383;
        int s = rem >> 13;
        int n = (rem >> 6) & 127;
        int w = rem & 63;
        const float* W;
        if (layer == 0)      W = s ? Wr0 : Wl0;
        else if (layer == 1) W = s ? Wr1 : Wl1;
        else                 W = s ? Wr2 : Wl2;
        float a = W[n * 128 + 2 * w];
        float b = W[n * 128 + 2 * w + 1];
        __half ha = __float2half_rn(a), hb = __float2half_rn(b);
        float ra = a - __half2float(ha), rb = b - __half2float(hb);
        __half la = __float2half_rn(ra), lb = __float2half_rn(rb);
        __half2 hp = __halves2half2(ha, hb);
        __half2 lp = __halves2half2(la, lb);
        uint32_t* Bp = (uint32_t*)g_Bp4[layer];
        Bp[(s * 128 + n) * 128 + w]      = *(uint32_t*)&hp;
        Bp[(s * 128 + n) * 128 + 64 + w] = *(uint32_t*)&lp;
    } else {
        int j = id - PREPN;
        if (j < XCONV) {
            int node = j >> 5;
            int f4 = j & 31;
            const float4 v = *(const float4*)(x + (size_t)node * C + f4 * 4);
            __half2 p0 = __floats2half2_rn(v.x, v.y);
            __half2 p1 = __floats2half2_rn(v.z, v.w);
            *(uint2*)(g_x16 + (size_t)node * C + f4 * 4) =
                make_uint2(*(uint32_t*)&p0, *(uint32_t*)&p1);
        } else {
            int k = j - XCONV;
            if (k < 32) {           // zero row NN of x16
                *(uint2*)(g_x16 + (size_t)NN * C + k * 4) = make_uint2(0u, 0u);
            } else if (k < 64) {    // zero row NN of h16
                *(uint2*)(g_h16 + (size_t)NN * C + (k - 32) * 4) = make_uint2(0u, 0u);
            }
        }
    }
}

// ---------------- degree + batch count (reads dst half of ei only) ----------
__global__ void count_kernel(const void* __restrict__ ei, const void* __restrict__ batch) {
    int i = blockIdx.x * blockDim.x + threadIdx.x;
    const bool is64 = (g_is64 != 0);
    if (i < NE) {
        int d;
        if (is64) d = (int)((const long long*)ei)[NE + i];
        else      d = ((const int*)ei)[NE + i];
        atomicAdd(&g_cnt[d], 1);
    }
    if (i < NN) {
        int b;
        if (is64) b = (int)((const long long*)batch)[i];
        else      b = ((const int*)batch)[i];
        g_batch[i] = b;
        atomicAdd(&g_gcnt[b], 1);
    }
}

// ---------------- 3-stage parallel scan over PADDED degrees ------------------
__global__ void scan1() {
    __shared__ int red[256];
    const int tid = threadIdx.x;
    int i = blockIdx.x * 256 + tid;
    red[tid] = (i < NN) ? ((g_cnt[i] + 7) & ~7) : 0;
    __syncthreads();
    for (int s = 128; s > 0; s >>= 1) {
        if (tid < s) red[tid] += red[tid + s];
        __syncthreads();
    }
    if (tid == 0) g_part[blockIdx.x] = red[0];
}

__global__ void scan2() {
    __shared__ int sc[256];
    const int t = threadIdx.x;
    int v = (t < 196) ? g_part[t] : 0;
    sc[t] = v;
    __syncthreads();
    for (int d = 1; d < 256; d <<= 1) {
        int val = sc[t];
        int add = (t >= d) ? sc[t - d] : 0;
        __syncthreads();
        sc[t] = val + add;
        __syncthreads();
    }
    if (t < 196) g_pbase[t] = sc[t] - v;
    if (t == 195) g_off[NN] = sc[195];   // total padded edges
    if (t < NG) g_ginv[t] = 1.0f / fmaxf((float)g_gcnt[t], 1.0f);
}

__global__ void scan3() {
    __shared__ int sc[256];
    const int tid = threadIdx.x;
    int i = blockIdx.x * 256 + tid;
    int v = (i < NN) ? g_cnt[i] : 0;
    int pv = (v + 7) & ~7;
    sc[tid] = pv;
    __syncthreads();
    for (int d = 1; d < 256; d <<= 1) {
        int val = sc[tid];
        int add = (tid >= d) ? sc[tid - d] : 0;
        __syncthreads();
        sc[tid] = val + add;
        __syncthreads();
    }
    if (i < NN) {
        int excl = sc[tid] - pv + g_pbase[blockIdx.x];
        g_off[i] = excl;
        g_cur[i] = excl;
        g_inv[i] = 1.0f / fmaxf((float)v, 1.0f);
        for (int p = excl + v; p < excl + pv; p++) g_adj[p] = NN;  // padding -> zero row
    }
}

// ---------------- CSR fill (reads ei directly) -------------------------------
__global__ void fill_kernel(const void* __restrict__ ei) {
    int e = blockIdx.x * blockDim.x + threadIdx.x;
    if (e < NE) {
        int s, d;
        if (g_is64) {
            const long long* p = (const long long*)ei;
            s = (int)p[e];
            d = (int)p[NE + e];
        } else {
            const int* p = (const int*)ei;
            s = p[e];
            d = p[NE + e];
        }
        int pos = atomicAdd(&g_cur[d], 1);
        g_adj[pos] = s;
    }
}

// ---------------- mean aggregation: tail-free fp16 HADD2-tree batches --------
// warp per node, lane owns 4 channels. All batches full 8 edges (padding -> row NN).
__global__ void gather_kernel(int in_sel) {
    const __half* hin = (in_sel == 0) ? g_x16 : g_h16;
    int gid = blockIdx.x * blockDim.x + threadIdx.x;
    int node = gid >> 5;
    int lane = gid & 31;
    if (node >= NN) return;
    const int beg = g_off[node];
    const int end = g_off[node + 1];
    const int co = lane * 4;
    const int4* adjv = (const int4*)g_adj;
    float2 fa = make_float2(0.f, 0.f);
    float2 fb = make_float2(0.f, 0.f);
    for (int i = beg; i < end; i += 8) {
        const int q = i >> 2;
        int4 a0 = adjv[q];
        int4 a1 = adjv[q + 1];
        uint2 u0 = *(const uint2*)(hin + (size_t)a0.x * C + co);
        uint2 u1 = *(const uint2*)(hin + (size_t)a0.y * C + co);
        uint2 u2 = *(const uint2*)(hin + (size_t)a0.z * C + co);
        uint2 u3 = *(const uint2*)(hin + (size_t)a0.w * C + co);
        uint2 u4 = *(const uint2*)(hin + (size_t)a1.x * C + co);
        uint2 u5 = *(const uint2*)(hin + (size_t)a1.y * C + co);
        uint2 u6 = *(const uint2*)(hin + (size_t)a1.z * C + co);
        uint2 u7 = *(const uint2*)(hin + (size_t)a1.w * C + co);
        __half2 xs = __hadd2(
            __hadd2(__hadd2(*(__half2*)&u0.x, *(__half2*)&u1.x),
                    __hadd2(*(__half2*)&u2.x, *(__half2*)&u3.x)),
            __hadd2(__hadd2(*(__half2*)&u4.x, *(__half2*)&u5.x),
                    __hadd2(*(__half2*)&u6.x, *(__half2*)&u7.x)));
        __half2 ys = __hadd2(
            __hadd2(__hadd2(*(__half2*)&u0.y, *(__half2*)&u1.y),
                    __hadd2(*(__half2*)&u2.y, *(__half2*)&u3.y)),
            __hadd2(__hadd2(*(__half2*)&u4.y, *(__half2*)&u5.y),
                    __hadd2(*(__half2*)&u6.y, *(__half2*)&u7.y)));
        float2 f0 = __half22float2(xs);
        float2 f1 = __half22float2(ys);
        fa.x += f0.x; fa.y += f0.y;
        fb.x += f1.x; fb.y += f1.y;
    }
    const float s = g_inv[node];
    __half2 p0 = __floats2half2_rn(fa.x * s, fa.y * s);
    __half2 p1 = __floats2half2_rn(fb.x * s, fb.y * s);
    *(uint2*)(g_agg16 + (size_t)node * C + co) =
        make_uint2(*(uint32_t*)&p0, *(uint32_t*)&p1);
}

// ---------------- tensor-core SAGE layer (fp16, 2-pairing, dbl-buffered A) ---
#define RSA 68
#define A_WORDS (128 * RSA)        // 8704
#define RSB 132
#define B_WORDS (128 * RSB)        // 16896
#define SMEM_WORDS (2 * A_WORDS + 2 * B_WORDS)   // 51200 words = 200KB

__device__ __forceinline__ void lda_regs(uint4* v, const __half* src, int mbase, int tid) {
#pragma unroll
    for (int i = 0; i < 8; i++) {
        int id = tid + 256 * i;
        int r = id >> 4;
        int q = id & 15;
        int gr = mbase + r;
        if (gr >= NN) gr = 0;
        v[i] = *(const uint4*)(src + (size_t)gr * C + q * 8);
    }
}

__device__ __forceinline__ void sta_regs(uint32_t* As, const uint4* v, int tid) {
#pragma unroll
    for (int i = 0; i < 8; i++) {
        int id = tid + 256 * i;
        int r = id >> 4;
        int q = id & 15;
        *(uint4*)(As + r * RSA + q * 4) = v[i];
    }
}

__global__ void __launch_bounds__(256, 1) sage_gemm_mma(
    int layer, const float* __restrict__ bl)
{
    extern __shared__ uint32_t smem[];
    uint32_t* Asb[2] = {smem, smem + A_WORDS};
    uint32_t* B0s = smem + 2 * A_WORDS;
    uint32_t* B1s = B0s + B_WORDS;

    const __half* hsrc = (layer == 0) ? g_x16 : g_h16;

    const int tid = threadIdx.x;
    const int wid = tid >> 5;
    const int lane = tid & 31;
    const int gid = lane >> 2;
    const int tig = lane & 3;
    const int wr = wid & 3;
    const int wc = wid >> 2;

    // Load all B (2 sources x 128 n x 128 words), padded rows.
    {
        const uint4* Bp = g_Bp4[layer];
#pragma unroll
        for (int i = 0; i < 32; i++) {
            int id = tid + 256 * i;
            int s = id >> 12;
            int n = (id >> 5) & 127;
            int q = id & 31;
            uint4 v = Bp[id];
            *(uint4*)((s ? B1s : B0s) + n * RSB + q * 4) = v;
        }
    }

    uint4 pf[8];
    lda_regs(pf, g_agg16, blockIdx.x * 128, tid);
    sta_regs(Asb[0], pf, tid);
    __syncthreads();
    int cur = 0;

    for (int tile = blockIdx.x; tile < NT; tile += NCTA) {
        const int mbase = tile * 128;
        float acc[2][8][4];
#pragma unroll
        for (int m = 0; m < 2; m++)
#pragma unroll
            for (int nf = 0; nf < 8; nf++)
#pragma unroll
                for (int i = 0; i < 4; i++) acc[m][nf][i] = 0.0f;

        const int nt2 = tile + NCTA;
        const bool hasnext = (nt2 < NT);

#pragma unroll
        for (int s = 0; s < 2; s++) {
            if (s == 0) lda_regs(pf, hsrc, mbase, tid);
            else if (hasnext) lda_regs(pf, g_agg16, nt2 * 128, tid);

            const uint32_t* As = Asb[cur];
            const uint32_t* Bs = s ? B1s : B0s;
            const uint32_t* Aw = As + (wr * 32 + gid) * RSA + tig;
            const uint32_t* Bw = Bs + (wc * 64 + gid) * RSB + tig;
#pragma unroll
            for (int ks = 0; ks < 8; ks++) {
                uint32_t ah[2][4];
#pragma unroll
                for (int m = 0; m < 2; m++) {
                    const uint32_t* Am = Aw + (m * 16) * RSA + ks * 8;
                    ah[m][0] = Am[0];
                    ah[m][1] = Am[8 * RSA];
                    ah[m][2] = Am[4];
                    ah[m][3] = Am[8 * RSA + 4];
                }
                const uint32_t* Bq = Bw + ks * 8;
#pragma unroll
                for (int nf = 0; nf < 8; nf++) {
                    const uint32_t* Bn = Bq + nf * (8 * RSB);
                    uint32_t bh0 = Bn[0], bh1 = Bn[4];
                    uint32_t bl0 = Bn[64], bl1 = Bn[68];
#pragma unroll
                    for (int m = 0; m < 2; m++) {
                        mma_f16(acc[m][nf], ah[m][0], ah[m][1], ah[m][2], ah[m][3], bh0, bh1);
                        mma_f16(acc[m][nf], ah[m][0], ah[m][1], ah[m][2], ah[m][3], bl0, bl1);
                    }
                }
            }

            if (s == 1) {
#pragma unroll
                for (int m = 0; m < 2; m++) {
                    const int r0 = mbase + wr * 32 + m * 16 + gid;
                    const int r1 = r0 + 8;
#pragma unroll
                    for (int nf = 0; nf < 8; nf++) {
                        const int col = wc * 64 + nf * 8 + tig * 2;
                        const float2 bb = *(const float2*)(bl + col);
                        float v00 = fmaxf(acc[m][nf][0] + bb.x, 0.0f);
                        float v01 = fmaxf(acc[m][nf][1] + bb.y, 0.0f);
                        float v10 = fmaxf(acc[m][nf][2] + bb.x, 0.0f);
                        float v11 = fmaxf(acc[m][nf][3] + bb.y, 0.0f);
                        if (r0 < NN) {
                            __half2 p = __floats2half2_rn(v00, v01);
                            *(uint32_t*)(g_h16 + (size_t)r0 * C + col) = *(uint32_t*)&p;
                        }
                        if (r1 < NN) {
                            __half2 p = __floats2half2_rn(v10, v11);
                            *(uint32_t*)(g_h16 + (size_t)r1 * C + col) = *(uint32_t*)&p;
                        }
                    }
                }
            }

            if (s == 0 || hasnext) sta_regs(Asb[cur ^ 1], pf, tid);
            __syncthreads();
            cur ^= 1;
        }
    }
}

// ---------------- global mean pool: run-length over sorted batch (fp16 in) --
__global__ void pool_kernel() {
    int gid = blockIdx.x * blockDim.x + threadIdx.x;
    int warp = gid >> 5;
    int lane = gid & 31;
    int n0 = warp * 16;
    if (n0 >= NN) return;
    int cur = g_batch[n0];
    float4 acc = make_float4(0.f, 0.f, 0.f, 0.f);
    const int co = lane * 4;
#pragma unroll
    for (int k = 0; k < 16; k++) {
        int node = n0 + k;
        if (node >= NN) break;
        int b = g_batch[node];
        if (b != cur) {
            float* p = g_pool + cur * C + co;
            atomicAdd(p + 0, acc.x);
            atomicAdd(p + 1, acc.y);
            atomicAdd(p + 2, acc.z);
            atomicAdd(p + 3, acc.w);
            acc = make_float4(0.f, 0.f, 0.f, 0.f);
            cur = b;
        }
        uint2 u = *(const uint2*)(g_h16 + (size_t)node * C + co);
        float2 f0 = __half22float2(*(__half2*)&u.x);
        float2 f1 = __half22float2(*(__half2*)&u.y);
        acc.x += f0.x; acc.y += f0.y; acc.z += f1.x; acc.w += f1.y;
    }
    float* p = g_pool + cur * C + co;
    atomicAdd(p + 0, acc.x);
    atomicAdd(p + 1, acc.y);
    atomicAdd(p + 2, acc.z);
    atomicAdd(p + 3, acc.w);
}

// ---------------- head ------------------------------------------------------
__global__ void out_kernel(const float* __restrict__ W_lin,
                           const float* __restrict__ b_lin,
                           float* __restrict__ out) {
    int g = blockIdx.x;
    int c = threadIdx.x;
    __shared__ float sv[C];
    sv[c] = g_pool[g * C + c] * g_ginv[g];
    __syncthreads();
    if (c < OUTC) {
        float s = b_lin[c];
#pragma unroll
        for (int k = 0; k < C; k++) s += sv[k] * W_lin[c * C + k];
        out[g * OUTC + c] = s;
    }
}

// ---------------- launch ----------------------------------------------------
extern "C" void kernel_launch(void* const* d_in, const int* in_sizes, int n_in,
                              void* d_out, int out_size) {
    const float* x      = (const float*)d_in[0];
    const void*  ei     = d_in[1];
    const void*  batch  = d_in[2];
    const float* Wl[3]  = {(const float*)d_in[3], (const float*)d_in[6], (const float*)d_in[9]};
    const float* blv[3] = {(const float*)d_in[4], (const float*)d_in[7], (const float*)d_in[10]};
    const float* Wr[3]  = {(const float*)d_in[5], (const float*)d_in[8], (const float*)d_in[11]};
    const float* W_lin  = (const float*)d_in[12];
    const float* b_lin  = (const float*)d_in[13];
    float* out = (float*)d_out;

    static int smem_set = 0;
    if (!smem_set) {
        cudaFuncSetAttribute(sage_gemm_mma,
                             cudaFuncAttributeMaxDynamicSharedMemorySize,
                             SMEM_WORDS * 4);
        smem_set = 1;
    }

    const int TB = 256;
    const int gE = (NE + TB - 1) / TB;       // 2344
    const int gN = (NN + TB - 1) / TB;       // 196
    const int gW = (NN * 32 + TB - 1) / TB;  // 6250
    const int gP = ((NN + 15) / 16 * 32 + TB - 1) / TB;  // 391
    const int gI = (PREPN + XCONV + 64 + TB - 1) / TB;

    init_kernel<<<gI, TB>>>((const unsigned int*)ei,
                            Wl[0], Wr[0], Wl[1], Wr[1], Wl[2], Wr[2], x);
    count_kernel<<<gE, TB>>>(ei, batch);
    scan1<<<gN, TB>>>();
    scan2<<<1, 256>>>();
    scan3<<<gN, TB>>>();
    fill_kernel<<<gE, TB>>>(ei);

    const int in_sel[3] = {0, 1, 1};
    for (int l = 0; l < 3; l++) {
        gather_kernel<<<gW, TB>>>(in_sel[l]);
        sage_gemm_mma<<<NCTA, TB, SMEM_WORDS * 4>>>(l, blv[l]);
    }

    pool_kernel<<<gP, TB>>>();
    out_kernel<<<NG, C>>>(W_lin, b_lin, out);
}

// round 17
// speedup vs baseline: 1.0458x; 1.0458x over previous
#include <cuda_runtime.h>
#include <cuda_fp16.h>
#include <cstdint>
#include <cstddef>

#define NN   50000
#define NE   600000
#define C    128
#define NG   128
#define OUTC 10
#define NT   391          // ceil(NN/128) M-tiles
#define NCTA 148

// ---------------- scratch (static device globals: allocation-free) ----------
__device__ __half g_x16[NN * C];       // fp16 shadow of x
__device__ __half g_h16[NN * C];       // fp16 h (all layers; gather+GEMM+pool)
__device__ __half g_agg16[NN * C];     // fp16 aggregated means
__device__ float  g_inv[NN];
__device__ float  g_ginv[NG];
__device__ float  g_pool[NG * C];
// weights fp16 split: [layer][src(2)][n(128)][128 u32 words: 0..63 hi, 64..127 lo]
__device__ uint4 g_Bp4[3][8192];
__device__ int   g_cnt[NN];
__device__ int   g_gcnt[NG];
__device__ int   g_off[NN + 1];
__device__ int   g_cur[NN];
__device__ int   g_adj[NE];
__device__ int   g_batch[NN];
__device__ int   g_part[256];
__device__ int   g_pbase[256];
__device__ int   g_is64;

// ---------------- mma.sync fp16 m16n8k16, f32 accum --------------------------
__device__ __forceinline__ void mma_f16(float* d,
                                        uint32_t a0, uint32_t a1, uint32_t a2, uint32_t a3,
                                        uint32_t b0, uint32_t b1) {
    asm volatile(
        "mma.sync.aligned.m16n8k16.row.col.f32.f16.f16.f32 "
        "{%0,%1,%2,%3}, {%4,%5,%6,%7}, {%8,%9}, {%0,%1,%2,%3};"
        : "+f"(d[0]), "+f"(d[1]), "+f"(d[2]), "+f"(d[3])
        : "r"(a0), "r"(a1), "r"(a2), "r"(a3), "r"(b0), "r"(b1));
}

// ---------------- init: zero + detect + weight split + x16 convert -----------
#define PREPN (3 * 16384)
#define XCONV (NN * 32)
__global__ void init_kernel(const unsigned int* __restrict__ ei_words,
                            const float* __restrict__ Wl0, const float* __restrict__ Wr0,
                            const float* __restrict__ Wl1, const float* __restrict__ Wr1,
                            const float* __restrict__ Wl2, const float* __restrict__ Wr2,
                            const float* __restrict__ x) {
    int id = blockIdx.x * blockDim.x + threadIdx.x;
    if (id == 0) {
        int is64 = 1;
#pragma unroll
        for (int k = 0; k < 16; k++)
            if (ei_words[1 + 74 * k] != 0u) { is64 = 0; break; }
        g_is64 = is64;
    }
    if (id < NN) g_cnt[id] = 0;
    if (id < NG) g_gcnt[id] = 0;
    if (id < NG * C) g_pool[id] = 0.0f;

    if (id < PREPN) {
        int layer = id >> 14;
        int rem = id & 16383;
        int s = rem >> 13;
        int n = (rem >> 6) & 127;
        int w = rem & 63;
        const float* W;
        if (layer == 0)      W = s ? Wr0 : Wl0;
        else if (layer == 1) W = s ? Wr1 : Wl1;
        else                 W = s ? Wr2 : Wl2;
        float a = W[n * 128 + 2 * w];
        float b = W[n * 128 + 2 * w + 1];
        __half ha = __float2half_rn(a), hb = __float2half_rn(b);
        float ra = a - __half2float(ha), rb = b - __half2float(hb);
        __half la = __float2half_rn(ra), lb = __float2half_rn(rb);
        __half2 hp = __halves2half2(ha, hb);
        __half2 lp = __halves2half2(la, lb);
        uint32_t* Bp = (uint32_t*)g_Bp4[layer];
        Bp[(s * 128 + n) * 128 + w]      = *(uint32_t*)&hp;
        Bp[(s * 128 + n) * 128 + 64 + w] = *(uint32_t*)&lp;
    } else {
        int j = id - PREPN;
        if (j < XCONV) {
            int node = j >> 5;
            int f4 = j & 31;
            const float4 v = *(const float4*)(x + (size_t)node * C + f4 * 4);
            __half2 p0 = __floats2half2_rn(v.x, v.y);
            __half2 p1 = __floats2half2_rn(v.z, v.w);
            *(uint2*)(g_x16 + (size_t)node * C + f4 * 4) =
                make_uint2(*(uint32_t*)&p0, *(uint32_t*)&p1);
        }
    }
}

// ---------------- degree + batch count (reads dst half of ei only) ----------
__global__ void count_kernel(const void* __restrict__ ei, const void* __restrict__ batch) {
    int i = blockIdx.x * blockDim.x + threadIdx.x;
    const bool is64 = (g_is64 != 0);
    if (i < NE) {
        int d;
        if (is64) d = (int)((const long long*)ei)[NE + i];
        else      d = ((const int*)ei)[NE + i];
        atomicAdd(&g_cnt[d], 1);
    }
    if (i < NN) {
        int b;
        if (is64) b = (int)((const long long*)batch)[i];
        else      b = ((const int*)batch)[i];
        g_batch[i] = b;
        atomicAdd(&g_gcnt[b], 1);
    }
}

// ---------------- 3-stage parallel scan --------------------------------------
__global__ void scan1() {
    __shared__ int red[256];
    const int tid = threadIdx.x;
    int i = blockIdx.x * 256 + tid;
    red[tid] = (i < NN) ? g_cnt[i] : 0;
    __syncthreads();
    for (int s = 128; s > 0; s >>= 1) {
        if (tid < s) red[tid] += red[tid + s];
        __syncthreads();
    }
    if (tid == 0) g_part[blockIdx.x] = red[0];
}

__global__ void scan2() {
    __shared__ int sc[256];
    const int t = threadIdx.x;
    int v = (t < 196) ? g_part[t] : 0;
    sc[t] = v;
    __syncthreads();
    for (int d = 1; d < 256; d <<= 1) {
        int val = sc[t];
        int add = (t >= d) ? sc[t - d] : 0;
        __syncthreads();
        sc[t] = val + add;
        __syncthreads();
    }
    if (t < 196) g_pbase[t] = sc[t] - v;
    if (t == 0) g_off[NN] = NE;
    if (t < NG) g_ginv[t] = 1.0f / fmaxf((float)g_gcnt[t], 1.0f);
}

__global__ void scan3() {
    __shared__ int sc[256];
    const int tid = threadIdx.x;
    int i = blockIdx.x * 256 + tid;
    int v = (i < NN) ? g_cnt[i] : 0;
    sc[tid] = v;
    __syncthreads();
    for (int d = 1; d < 256; d <<= 1) {
        int val = sc[tid];
        int add = (tid >= d) ? sc[tid - d] : 0;
        __syncthreads();
        sc[tid] = val + add;
        __syncthreads();
    }
    if (i < NN) {
        int excl = sc[tid] - v + g_pbase[blockIdx.x];
        g_off[i] = excl;
        g_cur[i] = excl;
        g_inv[i] = 1.0f / fmaxf((float)v, 1.0f);
    }
}

// ---------------- CSR fill (reads ei directly) -------------------------------
__global__ void fill_kernel(const void* __restrict__ ei) {
    int e = blockIdx.x * blockDim.x + threadIdx.x;
    if (e < NE) {
        int s, d;
        if (g_is64) {
            const long long* p = (const long long*)ei;
            s = (int)p[e];
            d = (int)p[NE + e];
        } else {
            const int* p = (const int*)ei;
            s = p[e];
            d = p[NE + e];
        }
        int pos = atomicAdd(&g_cur[d], 1);
        g_adj[pos] = s;
    }
}

// ---------------- mean aggregation: fp16 pairwise-tree batches ---------------
// warp per node, lane owns 4 channels (uint2/edge). 8-edge + 4-edge batches
// accumulate in fp16 HADD2 trees, folded to f32 once per batch.
__global__ void gather_kernel(int in_sel) {
    const __half* hin = (in_sel == 0) ? g_x16 : g_h16;
    int gid = blockIdx.x * blockDim.x + threadIdx.x;
    int node = gid >> 5;
    int lane = gid & 31;
    if (node >= NN) return;
    const int beg = g_off[node];
    const int end = g_off[node + 1];
    const int co = lane * 4;
    float2 fa = make_float2(0.f, 0.f);
    float2 fb = make_float2(0.f, 0.f);
    int i = beg;
    const int n8 = beg + ((end - beg) & ~7);
    for (; i < n8; i += 8) {
        int sx[8];
#pragma unroll
        for (int k = 0; k < 8; k++) sx[k] = g_adj[i + k];
        uint2 u[8];
#pragma unroll
        for (int k = 0; k < 8; k++) u[k] = *(const uint2*)(hin + (size_t)sx[k] * C + co);
        __half2 xs = __hadd2(
            __hadd2(__hadd2(*(__half2*)&u[0].x, *(__half2*)&u[1].x),
                    __hadd2(*(__half2*)&u[2].x, *(__half2*)&u[3].x)),
            __hadd2(__hadd2(*(__half2*)&u[4].x, *(__half2*)&u[5].x),
                    __hadd2(*(__half2*)&u[6].x, *(__half2*)&u[7].x)));
        __half2 ys = __hadd2(
            __hadd2(__hadd2(*(__half2*)&u[0].y, *(__half2*)&u[1].y),
                    __hadd2(*(__half2*)&u[2].y, *(__half2*)&u[3].y)),
            __hadd2(__hadd2(*(__half2*)&u[4].y, *(__half2*)&u[5].y),
                    __hadd2(*(__half2*)&u[6].y, *(__half2*)&u[7].y)));
        float2 f0 = __half22float2(xs);
        float2 f1 = __half22float2(ys);
        fa.x += f0.x; fa.y += f0.y;
        fb.x += f1.x; fb.y += f1.y;
    }
    if (end - i >= 4) {
        int sx[4];
#pragma unroll
        for (int k = 0; k < 4; k++) sx[k] = g_adj[i + k];
        uint2 u[4];
#pragma unroll
        for (int k = 0; k < 4; k++) u[k] = *(const uint2*)(hin + (size_t)sx[k] * C + co);
        __half2 xs = __hadd2(__hadd2(*(__half2*)&u[0].x, *(__half2*)&u[1].x),
                             __hadd2(*(__half2*)&u[2].x, *(__half2*)&u[3].x));
        __half2 ys = __hadd2(__hadd2(*(__half2*)&u[0].y, *(__half2*)&u[1].y),
                             __hadd2(*(__half2*)&u[2].y, *(__half2*)&u[3].y));
        float2 f0 = __half22float2(xs);
        float2 f1 = __half22float2(ys);
        fa.x += f0.x; fa.y += f0.y;
        fb.x += f1.x; fb.y += f1.y;
        i += 4;
    }
    for (; i < end; i++) {
        int s0 = g_adj[i];
        uint2 u0 = *(const uint2*)(hin + (size_t)s0 * C + co);
        float2 f0 = __half22float2(*(__half2*)&u0.x);
        float2 f1 = __half22float2(*(__half2*)&u0.y);
        fa.x += f0.x; fa.y += f0.y;
        fb.x += f1.x; fb.y += f1.y;
    }
    const float s = g_inv[node];
    __half2 p0 = __floats2half2_rn(fa.x * s, fa.y * s);
    __half2 p1 = __floats2half2_rn(fb.x * s, fb.y * s);
    *(uint2*)(g_agg16 + (size_t)node * C + co) =
        make_uint2(*(uint32_t*)&p0, *(uint32_t*)&p1);
}

// ---------------- tensor-core SAGE layer (fp16, 2-pairing, dbl-buffered A) ---
#define RSA 68
#define A_WORDS (128 * RSA)        // 8704
#define RSB 132
#define B_WORDS (128 * RSB)        // 16896
#define SMEM_WORDS (2 * A_WORDS + 2 * B_WORDS)   // 51200 words = 200KB

__device__ __forceinline__ void lda_regs(uint4* v, const __half* src, int mbase, int tid) {
#pragma unroll
    for (int i = 0; i < 8; i++) {
        int id = tid + 256 * i;
        int r = id >> 4;
        int q = id & 15;
        int gr = mbase + r;
        if (gr >= NN) gr = 0;
        v[i] = *(const uint4*)(src + (size_t)gr * C + q * 8);
    }
}

__device__ __forceinline__ void sta_regs(uint32_t* As, const uint4* v, int tid) {
#pragma unroll
    for (int i = 0; i < 8; i++) {
        int id = tid + 256 * i;
        int r = id >> 4;
        int q = id & 15;
        *(uint4*)(As + r * RSA + q * 4) = v[i];
    }
}

__global__ void __launch_bounds__(256, 1) sage_gemm_mma(
    int layer, const float* __restrict__ bl)
{
    extern __shared__ uint32_t smem[];
    uint32_t* Asb[2] = {smem, smem + A_WORDS};
    uint32_t* B0s = smem + 2 * A_WORDS;
    uint32_t* B1s = B0s + B_WORDS;

    const __half* hsrc = (layer == 0) ? g_x16 : g_h16;

    const int tid = threadIdx.x;
    const int wid = tid >> 5;
    const int lane = tid & 31;
    const int gid = lane >> 2;
    const int tig = lane & 3;
    const int wr = wid & 3;
    const int wc = wid >> 2;

    // Load all B (2 sources x 128 n x 128 words), padded rows.
    {
        const uint4* Bp = g_Bp4[layer];
#pragma unroll
        for (int i = 0; i < 32; i++) {
            int id = tid + 256 * i;
            int s = id >> 12;
            int n = (id >> 5) & 127;
            int q = id & 31;
            uint4 v = Bp[id];
            *(uint4*)((s ? B1s : B0s) + n * RSB + q * 4) = v;
        }
    }

    uint4 pf[8];
    lda_regs(pf, g_agg16, blockIdx.x * 128, tid);
    sta_regs(Asb[0], pf, tid);
    __syncthreads();
    int cur = 0;

    for (int tile = blockIdx.x; tile < NT; tile += NCTA) {
        const int mbase = tile * 128;
        float acc[2][8][4];
#pragma unroll
        for (int m = 0; m < 2; m++)
#pragma unroll
            for (int nf = 0; nf < 8; nf++)
#pragma unroll
                for (int i = 0; i < 4; i++) acc[m][nf][i] = 0.0f;

        const int nt2 = tile + NCTA;
        const bool hasnext = (nt2 < NT);

#pragma unroll
        for (int s = 0; s < 2; s++) {
            if (s == 0) lda_regs(pf, hsrc, mbase, tid);
            else if (hasnext) lda_regs(pf, g_agg16, nt2 * 128, tid);

            const uint32_t* As = Asb[cur];
            const uint32_t* Bs = s ? B1s : B0s;
            const uint32_t* Aw = As + (wr * 32 + gid) * RSA + tig;
            const uint32_t* Bw = Bs + (wc * 64 + gid) * RSB + tig;
#pragma unroll
            for (int ks = 0; ks < 8; ks++) {
                uint32_t ah[2][4];
#pragma unroll
                for (int m = 0; m < 2; m++) {
                    const uint32_t* Am = Aw + (m * 16) * RSA + ks * 8;
                    ah[m][0] = Am[0];
                    ah[m][1] = Am[8 * RSA];
                    ah[m][2] = Am[4];
                    ah[m][3] = Am[8 * RSA + 4];
                }
                const uint32_t* Bq = Bw + ks * 8;
#pragma unroll
                for (int nf = 0; nf < 8; nf++) {
                    const uint32_t* Bn = Bq + nf * (8 * RSB);
                    uint32_t bh0 = Bn[0], bh1 = Bn[4];
                    uint32_t bl0 = Bn[64], bl1 = Bn[68];
#pragma unroll
                    for (int m = 0; m < 2; m++) {
                        mma_f16(acc[m][nf], ah[m][0], ah[m][1], ah[m][2], ah[m][3], bh0, bh1);
                        mma_f16(acc[m][nf], ah[m][0], ah[m][1], ah[m][2], ah[m][3], bl0, bl1);
                    }
                }
            }

            if (s == 1) {
#pragma unroll
                for (int m = 0; m < 2; m++) {
                    const int r0 = mbase + wr * 32 + m * 16 + gid;
                    const int r1 = r0 + 8;
#pragma unroll
                    for (int nf = 0; nf < 8; nf++) {
                        const int col = wc * 64 + nf * 8 + tig * 2;
                        const float2 bb = *(const float2*)(bl + col);
                        float v00 = fmaxf(acc[m][nf][0] + bb.x, 0.0f);
                        float v01 = fmaxf(acc[m][nf][1] + bb.y, 0.0f);
                        float v10 = fmaxf(acc[m][nf][2] + bb.x, 0.0f);
                        float v11 = fmaxf(acc[m][nf][3] + bb.y, 0.0f);
                        if (r0 < NN) {
                            __half2 p = __floats2half2_rn(v00, v01);
                            *(uint32_t*)(g_h16 + (size_t)r0 * C + col) = *(uint32_t*)&p;
                        }
                        if (r1 < NN) {
                            __half2 p = __floats2half2_rn(v10, v11);
                            *(uint32_t*)(g_h16 + (size_t)r1 * C + col) = *(uint32_t*)&p;
                        }
                    }
                }
            }

            if (s == 0 || hasnext) sta_regs(Asb[cur ^ 1], pf, tid);
            __syncthreads();
            cur ^= 1;
        }
    }
}

// ---------------- global mean pool: run-length over sorted batch (fp16 in) --
__global__ void pool_kernel() {
    int gid = blockIdx.x * blockDim.x + threadIdx.x;
    int warp = gid >> 5;
    int lane = gid & 31;
    int n0 = warp * 16;
    if (n0 >= NN) return;
    int cur = g_batch[n0];
    float4 acc = make_float4(0.f, 0.f, 0.f, 0.f);
    const int co = lane * 4;
#pragma unroll
    for (int k = 0; k < 16; k++) {
        int node = n0 + k;
        if (node >= NN) break;
        int b = g_batch[node];
        if (b != cur) {
            float* p = g_pool + cur * C + co;
            atomicAdd(p + 0, acc.x);
            atomicAdd(p + 1, acc.y);
            atomicAdd(p + 2, acc.z);
            atomicAdd(p + 3, acc.w);
            acc = make_float4(0.f, 0.f, 0.f, 0.f);
            cur = b;
        }
        uint2 u = *(const uint2*)(g_h16 + (size_t)node * C + co);
        float2 f0 = __half22float2(*(__half2*)&u.x);
        float2 f1 = __half22float2(*(__half2*)&u.y);
        acc.x += f0.x; acc.y += f0.y; acc.z += f1.x; acc.w += f1.y;
    }
    float* p = g_pool + cur * C + co;
    atomicAdd(p + 0, acc.x);
    atomicAdd(p + 1, acc.y);
    atomicAdd(p + 2, acc.z);
    atomicAdd(p + 3, acc.w);
}

// ---------------- head ------------------------------------------------------
__global__ void out_kernel(const float* __restrict__ W_lin,
                           const float* __restrict__ b_lin,
                           float* __restrict__ out) {
    int g = blockIdx.x;
    int c = threadIdx.x;
    __shared__ float sv[C];
    sv[c] = g_pool[g * C + c] * g_ginv[g];
    __syncthreads();
    if (c < OUTC) {
        float s = b_lin[c];
#pragma unroll
        for (int k = 0; k < C; k++) s += sv[k] * W_lin[c * C + k];
        out[g * OUTC + c] = s;
    }
}

// ---------------- launch ----------------------------------------------------
extern "C" void kernel_launch(void* const* d_in, const int* in_sizes, int n_in,
                              void* d_out, int out_size) {
    const float* x      = (const float*)d_in[0];
    const void*  ei     = d_in[1];
    const void*  batch  = d_in[2];
    const float* Wl[3]  = {(const float*)d_in[3], (const float*)d_in[6], (const float*)d_in[9]};
    const float* blv[3] = {(const float*)d_in[4], (const float*)d_in[7], (const float*)d_in[10]};
    const float* Wr[3]  = {(const float*)d_in[5], (const float*)d_in[8], (const float*)d_in[11]};
    const float* W_lin  = (const float*)d_in[12];
    const float* b_lin  = (const float*)d_in[13];
    float* out = (float*)d_out;

    static int smem_set = 0;
    if (!smem_set) {
        cudaFuncSetAttribute(sage_gemm_mma,
                             cudaFuncAttributeMaxDynamicSharedMemorySize,
                             SMEM_WORDS * 4);
        smem_set = 1;
    }

    const int TB = 256;
    const int gE = (NE + TB - 1) / TB;       // 2344
    const int gN = (NN + TB - 1) / TB;       // 196
    const int gW = (NN * 32 + TB - 1) / TB;  // 6250
    const int gP = ((NN + 15) / 16 * 32 + TB - 1) / TB;  // 391
    const int gI = (PREPN + XCONV + TB - 1) / TB;

    init_kernel<<<gI, TB>>>((const unsigned int*)ei,
                            Wl[0], Wr[0], Wl[1], Wr[1], Wl[2], Wr[2], x);
    count_kernel<<<gE, TB>>>(ei, batch);
    scan1<<<gN, TB>>>();
    scan2<<<1, 256>>>();
    scan3<<<gN, TB>>>();
    fill_kernel<<<gE, TB>>>(ei);

    const int in_sel[3] = {0, 1, 1};
    for (int l = 0; l < 3; l++) {
        gather_kernel<<<gW, TB>>>(in_sel[l]);
        sage_gemm_mma<<<NCTA, TB, SMEM_WORDS * 4>>>(l, blv[l]);
    }

    pool_kernel<<<gP, TB>>>();
    out_kernel<<<NG, C>>>(W_lin, b_lin, out);
}